// round 5
// baseline (speedup 1.0000x reference)
#include <cuda_runtime.h>
#include <math.h>

// Problem constants (fixed by setup_inputs)
#define BB 64      // batch
#define CC 256     // channels
#define DD 64      // 2D map side
#define TT 128     // total sentences (B * n, n = 2)
#define PP 2080    // triu proposals = D*(D+1)/2
#define TPL 128    // proposals per tile in main pass
#define KCH 32     // K chunk
#define NKC (CC / KCH)
#define NTILE 17   // ceil(PP / TPL)
#define NBLK (BB * NTILE)

typedef unsigned long long u64;

// ---------------- scratch (device globals; fully overwritten every launch) ---
__device__ int   g_pk[TT];              // argmax p (triu order) per t (K=1)
__device__ int   g_pkflat[TT];          // same, flat r*64+c position
__device__ float g_qn[BB * CC];         // normalized query feats (row-major)
__device__ float g_qnT[CC * BB];        // normalized query feats (C-major)
__device__ float g_sn[TT * CC];         // normalized sentence feats
__device__ float g_norm2k[TT];          // |v[b', pos_k(t)]|^2
__device__ float g_cross[BB];           // vk0 . vk1 raw dot per b'
__device__ float g_sTop[TT * BB];       // cosine(topk_vf[t], qf_n[b])
__device__ float g_qs[BB * TT];         // qf_n[b] . sf_n[t']
__device__ float g_totQpart[NBLK * BB]; // per-block partial: sum_p exp(10 s[q,b',p])
__device__ float g_posQpart[NBLK];      // per-block partial: pos subset (q==b', iou>0.5)
__device__ float g_negIpart[NBLK * 2];  // per-block partial intra neg-sums

// ---------------- f32x2 helpers (b64 regs via "l" constraint) ----------------
__device__ __forceinline__ u64 pack2(float lo, float hi) {
    u64 d; asm("mov.b64 %0, {%1, %2};" : "=l"(d) : "f"(lo), "f"(hi)); return d;
}
__device__ __forceinline__ void ffma2(u64& acc, u64 a, u64 b) {
    asm("fma.rn.f32x2 %0, %1, %2, %0;" : "+l"(acc) : "l"(a), "l"(b));
}
__device__ __forceinline__ float2 unpack2(u64 d) {
    float2 f; asm("mov.b64 {%0, %1}, %2;" : "=f"(f.x), "=f"(f.y) : "l"(d)); return f;
}

// ---------------- topk (K=1), coalesced full-row read + triu mask ----------
__global__ void k_topk(const float* __restrict__ iou2ds) {
    int t = blockIdx.x, tid = threadIdx.x;
    const float4* row = (const float4*)(iou2ds + (size_t)t * (DD * DD));
    float best = -1e30f; int bf = 0x3fffffff;
    for (int v = tid; v < 1024; v += 256) {
        float4 x = row[v];
        int f0 = v * 4;
        float vals[4] = {x.x, x.y, x.z, x.w};
        #pragma unroll
        for (int e = 0; e < 4; e++) {
            int f = f0 + e, r = f >> 6, c = f & 63;
            if (c >= r && vals[e] > best) { best = vals[e]; bf = f; }
        }
    }
    __shared__ float bv[256]; __shared__ int bx[256];
    bv[tid] = best; bx[tid] = bf;
    __syncthreads();
    for (int s = 128; s > 0; s >>= 1) {
        if (tid < s) {
            if (bv[tid + s] > bv[tid] ||
                (bv[tid + s] == bv[tid] && bx[tid + s] < bx[tid])) {
                bv[tid] = bv[tid + s]; bx[tid] = bx[tid + s];
            }
        }
        __syncthreads();
    }
    if (tid == 0) {
        int f = bx[0], r = f >> 6, c = f & 63;
        g_pk[t] = r * 64 - (r * (r - 1)) / 2 + (c - r);  // triu-order index
        g_pkflat[t] = f;
    }
}

// ---------------- per-b' topk-vector stats: norms + cross dot ----------------
__global__ void k_kstats(const float* __restrict__ vid) {
    int b = blockIdx.x, c = threadIdx.x;  // 256 threads
    int pk0 = g_pkflat[2 * b], pk1 = g_pkflat[2 * b + 1];
    const float* vb = vid + (size_t)b * CC * (DD * DD);
    float v0 = vb[(size_t)c * (DD * DD) + pk0];
    float v1 = vb[(size_t)c * (DD * DD) + pk1];
    float a = v0 * v0, d2 = v1 * v1, x = v0 * v1;
    for (int o = 16; o > 0; o >>= 1) {
        a  += __shfl_xor_sync(0xffffffffu, a, o);
        d2 += __shfl_xor_sync(0xffffffffu, d2, o);
        x  += __shfl_xor_sync(0xffffffffu, x, o);
    }
    __shared__ float sa[8], sd[8], sx[8];
    if ((c & 31) == 0) { sa[c >> 5] = a; sd[c >> 5] = d2; sx[c >> 5] = x; }
    __syncthreads();
    if (c == 0) {
        float ta = 0, td = 0, tc = 0;
        for (int w = 0; w < 8; w++) { ta += sa[w]; td += sd[w]; tc += sx[w]; }
        g_norm2k[2 * b] = ta; g_norm2k[2 * b + 1] = td; g_cross[b] = tc;
    }
}

// ---------------- row normalization (256 threads = C) ----------------
__device__ __forceinline__ float blk_sumsq(float v) {
    float s = v * v;
    for (int o = 16; o > 0; o >>= 1) s += __shfl_xor_sync(0xffffffffu, s, o);
    __shared__ float ws[8];
    int tid = threadIdx.x;
    if ((tid & 31) == 0) ws[tid >> 5] = s;
    __syncthreads();
    return ws[0] + ws[1] + ws[2] + ws[3] + ws[4] + ws[5] + ws[6] + ws[7];
}

__global__ void k_norm_q(const float* __restrict__ q) {
    int row = blockIdx.x, tid = threadIdx.x;
    float v = q[row * CC + tid];
    float inv = 1.0f / fmaxf(sqrtf(blk_sumsq(v)), 1e-12f);
    float nv = v * inv;
    g_qn[row * CC + tid] = nv;
    g_qnT[tid * BB + row] = nv;
}

__global__ void k_norm_s(const float* __restrict__ s) {
    int row = blockIdx.x, tid = threadIdx.x;
    float v = s[row * CC + tid];
    float inv = 1.0f / fmaxf(sqrtf(blk_sumsq(v)), 1e-12f);
    g_sn[row * CC + tid] = v * inv;
}

// ---------------- main fused pass ----------------
// grid (NTILE, BB), 256 threads. Block = (128-proposal tile, video b').
// Single gather of video; GEMM via packed fma.rn.f32x2; fused norm/intra dots.
__global__ void __launch_bounds__(256) k_main(const float* __restrict__ vid,
                                              const float* __restrict__ iou2d) {
    int tileIdx = blockIdx.x, bp = blockIdx.y;
    int p0 = tileIdx * TPL;
    int tid = threadIdx.x;

    __shared__ __align__(16) float Vs[KCH][TPL + 4];  // 32 x 132 (rows 528B, 16B-mult)
    __shared__ __align__(16) float Qs[KCH][BB + 4];   // 32 x 68
    __shared__ float vk0s[CC], vk1s[CC];
    __shared__ int   posArr[TPL];
    __shared__ float ioul[TPL];
    __shared__ float invn[TPL], i0s[TPL], i1s[TPL];
    __shared__ float statA[256], stat0[256], stat1[256];
    __shared__ float rbuf[16][64];
    __shared__ float redAll[256];

    const float* vb = vid + (size_t)bp * CC * (DD * DD);
    int t0 = 2 * bp, t1 = t0 + 1;
    int pkI0 = g_pk[t0], pkI1 = g_pk[t1];
    int pf0 = g_pkflat[t0], pf1 = g_pkflat[t1];

    vk0s[tid] = vb[(size_t)tid * (DD * DD) + pf0];
    vk1s[tid] = vb[(size_t)tid * (DD * DD) + pf1];
    if (tid < TPL) {
        int pg = p0 + tid;
        int pc = pg < PP ? pg : PP - 1;  // clamp; masked in epilogue
        int r = (int)(64.5f - sqrtf(64.5f * 64.5f - 2.0f * (float)pc));
        while (r > 0  && r * 64 - (r * (r - 1)) / 2 > pc) r--;
        while (r < 63 && (r + 1) * 64 - ((r + 1) * r) / 2 <= pc) r++;
        int start = r * 64 - (r * (r - 1)) / 2;
        int c = r + (pc - start);
        int pos = r * 64 + c;
        posArr[tid] = pos;
        ioul[tid] = iou2d[bp * (DD * DD) + pos];
    }
    __syncthreads();

    // register tile: 8p x 4q per thread; p pairs packed in f32x2
    int px = tid >> 4;      // 0..15 -> p base px*8
    int qy = tid & 15;      // 0..15 -> q base qy*4
    int pS = tid & 127;     // stats: own proposal
    int kh = tid >> 7;      // stats: k half
    u64 acc[4][4] = {};     // [j][pair]; 0 bits == (0.f, 0.f)
    float an = 0.f, a0 = 0.f, a1 = 0.f;

    for (int kc = 0; kc < NKC; kc++) {
        #pragma unroll
        for (int i = 0; i < 16; i++) {       // 32x128 V tile
            int idx = tid + i * 256, k = idx >> 7, p = idx & 127;
            Vs[k][p] = vb[(kc * KCH + k) * (DD * DD) + posArr[p]];
        }
        #pragma unroll
        for (int i = 0; i < 8; i++) {        // 32x64 Q tile (C-major global)
            int idx = tid + i * 256, k = idx >> 6, q = idx & 63;
            Qs[k][q] = g_qnT[(kc * KCH + k) * BB + q];
        }
        __syncthreads();

        // fused stats: 16 k per thread from shared
        #pragma unroll
        for (int kk = 0; kk < 16; kk++) {
            int k = kh * 16 + kk;
            float v = Vs[k][pS];
            an += v * v;
            a0 += v * vk0s[kc * KCH + k];
            a1 += v * vk1s[kc * KCH + k];
        }

        // GEMM: C[p,q] += sum_k V[k,p] * Q[k,q]
        #pragma unroll 8
        for (int k = 0; k < KCH; k++) {
            ulonglong2 aA = *(const ulonglong2*)&Vs[k][px * 8];
            ulonglong2 aB = *(const ulonglong2*)&Vs[k][px * 8 + 4];
            float4 bq = *(const float4*)&Qs[k][qy * 4];
            u64 b0 = pack2(bq.x, bq.x), b1 = pack2(bq.y, bq.y);
            u64 b2 = pack2(bq.z, bq.z), b3 = pack2(bq.w, bq.w);
            ffma2(acc[0][0], aA.x, b0); ffma2(acc[0][1], aA.y, b0);
            ffma2(acc[0][2], aB.x, b0); ffma2(acc[0][3], aB.y, b0);
            ffma2(acc[1][0], aA.x, b1); ffma2(acc[1][1], aA.y, b1);
            ffma2(acc[1][2], aB.x, b1); ffma2(acc[1][3], aB.y, b1);
            ffma2(acc[2][0], aA.x, b2); ffma2(acc[2][1], aA.y, b2);
            ffma2(acc[2][2], aB.x, b2); ffma2(acc[2][3], aB.y, b2);
            ffma2(acc[3][0], aA.x, b3); ffma2(acc[3][1], aA.y, b3);
            ffma2(acc[3][2], aB.x, b3); ffma2(acc[3][3], aB.y, b3);
        }
        __syncthreads();
    }

    // combine stats halves
    statA[tid] = an; stat0[tid] = a0; stat1[tid] = a1;
    __syncthreads();
    if (tid < TPL) {
        float n2 = statA[tid] + statA[tid + 128];
        invn[tid] = 1.0f / fmaxf(sqrtf(n2), 1e-12f);
        i0s[tid] = stat0[tid] + stat0[tid + 128];
        i1s[tid] = stat1[tid] + stat1[tid + 128];
    }
    __syncthreads();

    // epilogue: scores, exps, partial sums
    float tsum[4] = {0.f, 0.f, 0.f, 0.f};
    float posAcc = 0.f;
    int qbase = qy * 4;
    #pragma unroll
    for (int i = 0; i < 4; i++) {
        #pragma unroll
        for (int h = 0; h < 2; h++) {
            int p = px * 8 + 2 * i + h;
            int pg = p0 + p;
            bool valid = pg < PP;
            float inv = invn[p];
            bool posm = valid && (ioul[p] > 0.5f);
            bool is0 = (pg == pkI0), is1 = (pg == pkI1);
            #pragma unroll
            for (int j = 0; j < 4; j++) {
                float2 u = unpack2(acc[j][i]);
                float s = (h ? u.y : u.x) * inv;
                float e = valid ? __expf(10.0f * s) : 0.f;
                tsum[j] += e;
                if ((qbase + j) == bp && posm) posAcc += e;
                if (is0) g_sTop[t0 * BB + qbase + j] = s;
                if (is1) g_sTop[t1 * BB + qbase + j] = s;
            }
        }
    }
    #pragma unroll
    for (int j = 0; j < 4; j++) rbuf[px][qbase + j] = tsum[j];
    redAll[tid] = posAcc;
    __syncthreads();

    int blk = bp * NTILE + tileIdx;
    if (tid < 64) {
        float s = 0.f;
        #pragma unroll
        for (int r = 0; r < 16; r++) s += rbuf[r][tid];
        g_totQpart[blk * BB + tid] = s;
    }
    for (int s = 128; s > 0; s >>= 1) {
        if (tid < s) redAll[tid] += redAll[tid + s];
        __syncthreads();
    }
    if (tid == 0) g_posQpart[blk] = redAll[0];
    __syncthreads();

    if (tid < TPL) {
        int pg = p0 + tid;
        bool negm = (pg < PP) && (ioul[tid] < 0.5f);
        float invk0 = 1.0f / fmaxf(sqrtf(g_norm2k[t0]), 1e-12f);
        float invk1 = 1.0f / fmaxf(sqrtf(g_norm2k[t1]), 1e-12f);
        statA[tid] = negm ? __expf(10.0f * i0s[tid] * invn[tid] * invk0) : 0.f;
        stat0[tid] = negm ? __expf(10.0f * i1s[tid] * invn[tid] * invk1) : 0.f;
    }
    __syncthreads();
    if (tid < 2) {
        const float* src = tid ? stat0 : statA;
        float s = 0.f;
        for (int p = 0; p < TPL; p++) s += src[p];
        g_negIpart[blk * 2 + tid] = s;
    }
}

// ---------------- qf_n @ sf_n^T (tiny) ----------------
__global__ void k_qs() {
    int b = blockIdx.x, tid = threadIdx.x;  // 256 threads
    __shared__ float qsh[CC];
    qsh[tid] = g_qn[b * CC + tid];
    __syncthreads();
    int w = tid >> 5, lane = tid & 31;
    for (int t2 = w; t2 < TT; t2 += 8) {
        float a = 0.f;
        for (int c = lane; c < CC; c += 32) a += qsh[c] * g_sn[t2 * CC + c];
        for (int o = 16; o > 0; o >>= 1) a += __shfl_xor_sync(0xffffffffu, a, o);
        if (lane == 0) g_qs[b * TT + t2] = a;
    }
}

// ---------------- final: assemble the 4 losses ----------------
__global__ void k_final(float* __restrict__ out) {
    __shared__ float totQ4[BB][4];
    __shared__ float totQ[BB], posQ[BB], negI[TT];
    __shared__ float red[256];
    int tid = threadIdx.x;  // 256

    {   // totQ: 4-way split over the 1088 blocks
        int q = tid >> 2, part = tid & 3;
        float s = 0.f;
        for (int blk = part; blk < NBLK; blk += 4) s += g_totQpart[blk * BB + q];
        totQ4[q][part] = s;
    }
    if (tid < BB) {
        float sp = 0.f;
        for (int ti = 0; ti < NTILE; ti++) sp += g_posQpart[tid * NTILE + ti];
        posQ[tid] = sp;
    }
    if (tid < TT) {
        int b = tid >> 1, j = tid & 1;
        float s = 0.f;
        for (int ti = 0; ti < NTILE; ti++) s += g_negIpart[(b * NTILE + ti) * 2 + j];
        negI[tid] = s;
    }
    __syncthreads();
    if (tid < BB) totQ[tid] = totQ4[tid][0] + totQ4[tid][1] + totQ4[tid][2] + totQ4[tid][3];
    __syncthreads();

    float vals[4] = {0.f, 0.f, 0.f, 0.f};
    if (tid < TT) {
        int b = tid >> 1;  // scatter_idx[t] = t/2
        // inter_video
        float pos = g_sTop[tid * BB + b];
        float pe = __expf(10.f * pos);
        float ns = 0.f;
        for (int q = 0; q < BB; q++)
            if (q != b) ns += __expf(10.f * g_sTop[tid * BB + q]);
        vals[0] = -(10.f * pos - logf(pe + ns));
        // inter_query (neg = total - pos-subset)
        vals[1] = -(10.f * pos - logf(pe + (totQ[b] - posQ[b])));
        // intra_video
        float inv0 = 1.f / fmaxf(sqrtf(g_norm2k[2 * b]), 1e-12f);
        float inv1 = 1.f / fmaxf(sqrtf(g_norm2k[2 * b + 1]), 1e-12f);
        float crossn = g_cross[b] * inv0 * inv1;
        float invt = (tid & 1) ? inv1 : inv0;
        float selfn = g_norm2k[tid] * invt * invt;
        float nI = negI[tid];
        vals[2] = -(10.f * selfn  - logf(__expf(10.f * selfn)  + nI))
                + -(10.f * crossn - logf(__expf(10.f * crossn) + nI));
        // intra_query
        float posq = g_qs[b * TT + tid];
        float nsq = 0.f;
        for (int t2 = 0; t2 < TT; t2++)
            if ((t2 >> 1) != b) nsq += __expf(10.f * g_qs[b * TT + t2]);
        vals[3] = -(10.f * posq - logf(__expf(10.f * posq) + nsq));
    }
    const float divi[4] = {128.f, 128.f, 256.f, 128.f};
    for (int m = 0; m < 4; m++) {
        red[tid] = vals[m];
        __syncthreads();
        for (int s = 128; s > 0; s >>= 1) {
            if (tid < s) red[tid] += red[tid + s];
            __syncthreads();
        }
        if (tid == 0) out[m] = red[0] / divi[m];
        __syncthreads();
    }
}

// ---------------- launch ----------------
// Order chosen so ncu's skip-window lands on k_main (4th app launch).
extern "C" void kernel_launch(void* const* d_in, const int* in_sizes, int n_in,
                              void* d_out, int out_size) {
    const float* vid    = (const float*)d_in[0];  // (B, C, D, D)
    const float* qf     = (const float*)d_in[1];  // (B, C)
    const float* sf     = (const float*)d_in[2];  // (T, C)
    const float* iou2d  = (const float*)d_in[3];  // (B, D, D)
    const float* iou2ds = (const float*)d_in[4];  // (T, D, D)
    (void)in_sizes; (void)n_in; (void)out_size;

    k_topk  <<<TT, 256>>>(iou2ds);
    k_kstats<<<BB, 256>>>(vid);
    k_norm_q<<<BB, 256>>>(qf);
    k_main  <<<dim3(NTILE, BB), 256>>>(vid, iou2d);
    k_norm_s<<<TT, 256>>>(sf);
    k_qs    <<<BB, 256>>>();
    k_final <<<1, 256>>>((float*)d_out);
}

// round 6
// speedup vs baseline: 1.0433x; 1.0433x over previous
#include <cuda_runtime.h>
#include <math.h>

// Problem constants (fixed by setup_inputs)
#define BB 64      // batch
#define CC 256     // channels
#define DD 64      // 2D map side
#define TT 128     // total sentences (B * n, n = 2)
#define PP 2080    // triu proposals = D*(D+1)/2
#define TPL 256    // proposals per tile in main pass
#define KCH 16     // K chunk
#define NKC (CC / KCH)
#define NTILE 9    // ceil(PP / TPL)
#define NBLK (BB * NTILE)

typedef unsigned long long u64;

// ---------------- scratch (device globals; fully overwritten every launch) ---
__device__ int   g_pk[TT];              // argmax p (triu order) per t (K=1)
__device__ int   g_pkflat[TT];          // same, flat r*64+c position
__device__ float g_qn[BB * CC];         // normalized query feats (row-major)
__device__ float g_qnT[CC * BB];        // normalized query feats (C-major)
__device__ float g_sn[TT * CC];         // normalized sentence feats
__device__ float g_norm2k[TT];          // |v[b', pos_k(t)]|^2
__device__ float g_cross[BB];           // vk0 . vk1 raw dot per b'
__device__ float g_sTop[TT * BB];       // cosine(topk_vf[t], qf_n[b])
__device__ float g_qs[BB * TT];         // qf_n[b] . sf_n[t']
__device__ float g_totQpart[NBLK * BB]; // per-block partial: sum_p exp(10 s[q,b',p])
__device__ float g_posQpart[NBLK];      // per-block partial: pos subset (q==b', iou>0.5)
__device__ float g_negIpart[NBLK * 2];  // per-block partial intra neg-sums

// ---------------- f32x2 helpers (b64 regs via "l" constraint) ----------------
__device__ __forceinline__ u64 pack2(float lo, float hi) {
    u64 d; asm("mov.b64 %0, {%1, %2};" : "=l"(d) : "f"(lo), "f"(hi)); return d;
}
__device__ __forceinline__ void ffma2(u64& acc, u64 a, u64 b) {
    asm("fma.rn.f32x2 %0, %1, %2, %0;" : "+l"(acc) : "l"(a), "l"(b));
}
__device__ __forceinline__ float2 unpack2(u64 d) {
    float2 f; asm("mov.b64 {%0, %1}, %2;" : "=f"(f.x), "=f"(f.y) : "l"(d)); return f;
}

// ---------------- topk (K=1) + topk-vector stats, fused per b' ----------------
__global__ void k_topkstats(const float* __restrict__ iou2ds,
                            const float* __restrict__ vid) {
    int b = blockIdx.x, tid = threadIdx.x;  // 256 threads
    __shared__ float bv[256]; __shared__ int bx[256];
    __shared__ int pkf[2];

    for (int j = 0; j < 2; j++) {
        int t = 2 * b + j;
        const float4* row = (const float4*)(iou2ds + (size_t)t * (DD * DD));
        float best = -1e30f; int bf = 0x3fffffff;
        for (int v = tid; v < 1024; v += 256) {
            float4 x = row[v];
            int f0 = v * 4;
            float vals[4] = {x.x, x.y, x.z, x.w};
            #pragma unroll
            for (int e = 0; e < 4; e++) {
                int f = f0 + e, r = f >> 6, c = f & 63;
                if (c >= r && vals[e] > best) { best = vals[e]; bf = f; }
            }
        }
        bv[tid] = best; bx[tid] = bf;
        __syncthreads();
        for (int s = 128; s > 0; s >>= 1) {
            if (tid < s) {
                if (bv[tid + s] > bv[tid] ||
                    (bv[tid + s] == bv[tid] && bx[tid + s] < bx[tid])) {
                    bv[tid] = bv[tid + s]; bx[tid] = bx[tid + s];
                }
            }
            __syncthreads();
        }
        if (tid == 0) {
            int f = bx[0], r = f >> 6, c = f & 63;
            g_pk[t] = r * 64 - (r * (r - 1)) / 2 + (c - r);  // triu-order index
            g_pkflat[t] = f;
            pkf[j] = f;
        }
        __syncthreads();
    }

    // stats on the two topk vectors
    int pk0 = pkf[0], pk1 = pkf[1];
    const float* vb = vid + (size_t)b * CC * (DD * DD);
    float v0 = vb[(size_t)tid * (DD * DD) + pk0];
    float v1 = vb[(size_t)tid * (DD * DD) + pk1];
    float a = v0 * v0, d2 = v1 * v1, x = v0 * v1;
    for (int o = 16; o > 0; o >>= 1) {
        a  += __shfl_xor_sync(0xffffffffu, a, o);
        d2 += __shfl_xor_sync(0xffffffffu, d2, o);
        x  += __shfl_xor_sync(0xffffffffu, x, o);
    }
    __shared__ float sa[8], sd[8], sx[8];
    if ((tid & 31) == 0) { sa[tid >> 5] = a; sd[tid >> 5] = d2; sx[tid >> 5] = x; }
    __syncthreads();
    if (tid == 0) {
        float ta = 0, td = 0, tc = 0;
        for (int w = 0; w < 8; w++) { ta += sa[w]; td += sd[w]; tc += sx[w]; }
        g_norm2k[2 * b] = ta; g_norm2k[2 * b + 1] = td; g_cross[b] = tc;
    }
}

// ---------------- row normalization (256 threads = C) ----------------
__device__ __forceinline__ float blk_sumsq(float v) {
    float s = v * v;
    for (int o = 16; o > 0; o >>= 1) s += __shfl_xor_sync(0xffffffffu, s, o);
    __shared__ float ws[8];
    int tid = threadIdx.x;
    if ((tid & 31) == 0) ws[tid >> 5] = s;
    __syncthreads();
    return ws[0] + ws[1] + ws[2] + ws[3] + ws[4] + ws[5] + ws[6] + ws[7];
}

__global__ void k_norm_q(const float* __restrict__ q) {
    int row = blockIdx.x, tid = threadIdx.x;
    float v = q[row * CC + tid];
    float inv = 1.0f / fmaxf(sqrtf(blk_sumsq(v)), 1e-12f);
    float nv = v * inv;
    g_qn[row * CC + tid] = nv;
    g_qnT[tid * BB + row] = nv;
}

__global__ void k_norm_s(const float* __restrict__ s) {
    int row = blockIdx.x, tid = threadIdx.x;
    float v = s[row * CC + tid];
    float inv = 1.0f / fmaxf(sqrtf(blk_sumsq(v)), 1e-12f);
    g_sn[row * CC + tid] = v * inv;
}

// ---------------- main fused pass ----------------
// grid (NTILE, BB), 256 threads. Block = (256-proposal tile, video b').
// Thread tid gathers proposal p=tid for all k (stats ride the gather regs).
// GEMM register tile 8p x 8q via packed fma.rn.f32x2.
__global__ void __launch_bounds__(256, 2) k_main(const float* __restrict__ vid,
                                                 const float* __restrict__ iou2d) {
    int tileIdx = blockIdx.x, bp = blockIdx.y;
    int p0 = tileIdx * TPL;
    int tid = threadIdx.x;

    __shared__ __align__(16) float Vs[KCH][TPL + 4];  // 16 x 260 (rows 1040B, 16B-mult)
    __shared__ __align__(16) float Qs[KCH][BB + 4];   // 16 x 68
    __shared__ float vk0s[CC], vk1s[CC];
    __shared__ float ioul[TPL];
    __shared__ float invn[TPL];
    __shared__ float rbuf[32][64];                    // 8KB reduce buffer
    __shared__ float redAll[256];

    const float* vb = vid + (size_t)bp * CC * (DD * DD);
    int t0 = 2 * bp, t1 = t0 + 1;
    int pkI0 = g_pk[t0], pkI1 = g_pk[t1];
    int pf0 = g_pkflat[t0], pf1 = g_pkflat[t1];

    vk0s[tid] = vb[(size_t)tid * (DD * DD) + pf0];
    vk1s[tid] = vb[(size_t)tid * (DD * DD) + pf1];

    // this thread's proposal (p = tid)
    int pg = p0 + tid;
    int pc = pg < PP ? pg : PP - 1;  // clamp; masked later
    int r = (int)(64.5f - sqrtf(64.5f * 64.5f - 2.0f * (float)pc));
    while (r > 0  && r * 64 - (r * (r - 1)) / 2 > pc) r--;
    while (r < 63 && (r + 1) * 64 - ((r + 1) * r) / 2 <= pc) r++;
    int start = r * 64 - (r * (r - 1)) / 2;
    int myPos = r * 64 + (r + (pc - start));
    float myIou = iou2d[bp * (DD * DD) + myPos];
    ioul[tid] = myIou;
    __syncthreads();

    int pgroup = tid >> 3;   // 0..31 -> p base pgroup*8
    int qgroup = tid & 7;    // 0..7  -> q base qgroup*8
    u64 acc[8][4] = {};      // [j][pair]; 0 bits == (0.f, 0.f)
    float an = 0.f, a0 = 0.f, a1 = 0.f;
    const float* gp = vb + myPos;

    for (int kc = 0; kc < NKC; kc++) {
        int kb = kc * KCH;
        // V tile: thread owns p=tid; gather 16 k's, stats ride along
        #pragma unroll
        for (int k = 0; k < KCH; k++) {
            float v = gp[(size_t)(kb + k) * (DD * DD)];
            Vs[k][tid] = v;
            float w0 = vk0s[kb + k], w1 = vk1s[kb + k];
            an += v * v; a0 += v * w0; a1 += v * w1;
        }
        // Q tile: 16x64, 4 per thread (C-major global)
        #pragma unroll
        for (int i = 0; i < 4; i++) {
            int idx = tid + i * 256, k = idx >> 6, q = idx & 63;
            Qs[k][q] = g_qnT[(kb + k) * BB + q];
        }
        __syncthreads();

        // GEMM: C[p,q] += sum_k V[k,p] * Q[k,q]; 64 MACs per thread per k
        #pragma unroll
        for (int k = 0; k < KCH; k++) {
            ulonglong2 aA = *(const ulonglong2*)&Vs[k][pgroup * 8];
            ulonglong2 aB = *(const ulonglong2*)&Vs[k][pgroup * 8 + 4];
            float4 q0 = *(const float4*)&Qs[k][qgroup * 8];
            float4 q1 = *(const float4*)&Qs[k][qgroup * 8 + 4];
            u64 b0 = pack2(q0.x, q0.x), b1 = pack2(q0.y, q0.y);
            u64 b2 = pack2(q0.z, q0.z), b3 = pack2(q0.w, q0.w);
            u64 b4 = pack2(q1.x, q1.x), b5 = pack2(q1.y, q1.y);
            u64 b6 = pack2(q1.z, q1.z), b7 = pack2(q1.w, q1.w);
            #pragma unroll
            for (int i = 0; i < 4; i++) {
                u64 av = (i == 0) ? aA.x : (i == 1) ? aA.y : (i == 2) ? aB.x : aB.y;
                ffma2(acc[0][i], av, b0); ffma2(acc[1][i], av, b1);
                ffma2(acc[2][i], av, b2); ffma2(acc[3][i], av, b3);
                ffma2(acc[4][i], av, b4); ffma2(acc[5][i], av, b5);
                ffma2(acc[6][i], av, b6); ffma2(acc[7][i], av, b7);
            }
        }
        __syncthreads();
    }

    // per-thread stats complete (thread owns p = tid)
    float myInv = 1.0f / fmaxf(sqrtf(an), 1e-12f);
    invn[tid] = myInv;
    __syncthreads();

    // epilogue: scores, exps, partial sums
    float tsum[8] = {};
    float posAcc = 0.f;
    int qbase = qgroup * 8;
    #pragma unroll
    for (int i = 0; i < 4; i++) {
        #pragma unroll
        for (int h = 0; h < 2; h++) {
            int p = pgroup * 8 + 2 * i + h;
            int pgl = p0 + p;
            bool valid = pgl < PP;
            float inv = invn[p];
            bool posm = valid && (ioul[p] > 0.5f);
            bool is0 = (pgl == pkI0), is1 = (pgl == pkI1);
            #pragma unroll
            for (int j = 0; j < 8; j++) {
                float2 u = unpack2(acc[j][i]);
                float s = (h ? u.y : u.x) * inv;
                float e = valid ? __expf(10.0f * s) : 0.f;
                tsum[j] += e;
                if ((qbase + j) == bp && posm) posAcc += e;
                if (is0) g_sTop[t0 * BB + qbase + j] = s;
                if (is1) g_sTop[t1 * BB + qbase + j] = s;
            }
        }
    }
    #pragma unroll
    for (int j = 0; j < 8; j++) rbuf[pgroup][qbase + j] = tsum[j];
    redAll[tid] = posAcc;
    __syncthreads();

    int blk = bp * NTILE + tileIdx;
    if (tid < 64) {
        float s = 0.f;
        #pragma unroll
        for (int rr = 0; rr < 32; rr++) s += rbuf[rr][tid];
        g_totQpart[blk * BB + tid] = s;
    }
    for (int s = 128; s > 0; s >>= 1) {
        if (tid < s) redAll[tid] += redAll[tid + s];
        __syncthreads();
    }
    if (tid == 0) g_posQpart[blk] = redAll[0];
    __syncthreads();  // rbuf fully consumed

    // intra-video neg sums (own p = tid, stats in regs)
    {
        bool negm = (pg < PP) && (myIou < 0.5f);
        float invk0 = 1.0f / fmaxf(sqrtf(g_norm2k[t0]), 1e-12f);
        float invk1 = 1.0f / fmaxf(sqrtf(g_norm2k[t1]), 1e-12f);
        float* fb = &rbuf[0][0];
        fb[tid]       = negm ? __expf(10.0f * a0 * myInv * invk0) : 0.f;
        fb[256 + tid] = negm ? __expf(10.0f * a1 * myInv * invk1) : 0.f;
    }
    __syncthreads();
    if (tid < 2) {
        const float* src = &rbuf[0][0] + tid * 256;
        float s = 0.f;
        for (int p = 0; p < 256; p++) s += src[p];
        g_negIpart[blk * 2 + tid] = s;
    }
}

// ---------------- qf_n @ sf_n^T (tiny) ----------------
__global__ void k_qs() {
    int b = blockIdx.x, tid = threadIdx.x;  // 256 threads
    __shared__ float qsh[CC];
    qsh[tid] = g_qn[b * CC + tid];
    __syncthreads();
    int w = tid >> 5, lane = tid & 31;
    for (int t2 = w; t2 < TT; t2 += 8) {
        float a = 0.f;
        for (int c = lane; c < CC; c += 32) a += qsh[c] * g_sn[t2 * CC + c];
        for (int o = 16; o > 0; o >>= 1) a += __shfl_xor_sync(0xffffffffu, a, o);
        if (lane == 0) g_qs[b * TT + t2] = a;
    }
}

// ---------------- final: assemble the 4 losses ----------------
__global__ void k_final(float* __restrict__ out) {
    __shared__ float totQ4[BB][4];
    __shared__ float totQ[BB], posQ[BB], negI[TT];
    __shared__ float red[256];
    int tid = threadIdx.x;  // 256

    {   // totQ: 4-way split over the 576 blocks
        int q = tid >> 2, part = tid & 3;
        float s = 0.f;
        for (int blk = part; blk < NBLK; blk += 4) s += g_totQpart[blk * BB + q];
        totQ4[q][part] = s;
    }
    if (tid < BB) {
        float sp = 0.f;
        for (int ti = 0; ti < NTILE; ti++) sp += g_posQpart[tid * NTILE + ti];
        posQ[tid] = sp;
    }
    if (tid < TT) {
        int b = tid >> 1, j = tid & 1;
        float s = 0.f;
        for (int ti = 0; ti < NTILE; ti++) s += g_negIpart[(b * NTILE + ti) * 2 + j];
        negI[tid] = s;
    }
    __syncthreads();
    if (tid < BB) totQ[tid] = totQ4[tid][0] + totQ4[tid][1] + totQ4[tid][2] + totQ4[tid][3];
    __syncthreads();

    float vals[4] = {0.f, 0.f, 0.f, 0.f};
    if (tid < TT) {
        int b = tid >> 1;  // scatter_idx[t] = t/2
        // inter_video
        float pos = g_sTop[tid * BB + b];
        float pe = __expf(10.f * pos);
        float ns = 0.f;
        for (int q = 0; q < BB; q++)
            if (q != b) ns += __expf(10.f * g_sTop[tid * BB + q]);
        vals[0] = -(10.f * pos - logf(pe + ns));
        // inter_query (neg = total - pos-subset)
        vals[1] = -(10.f * pos - logf(pe + (totQ[b] - posQ[b])));
        // intra_video
        float inv0 = 1.f / fmaxf(sqrtf(g_norm2k[2 * b]), 1e-12f);
        float inv1 = 1.f / fmaxf(sqrtf(g_norm2k[2 * b + 1]), 1e-12f);
        float crossn = g_cross[b] * inv0 * inv1;
        float invt = (tid & 1) ? inv1 : inv0;
        float selfn = g_norm2k[tid] * invt * invt;
        float nI = negI[tid];
        vals[2] = -(10.f * selfn  - logf(__expf(10.f * selfn)  + nI))
                + -(10.f * crossn - logf(__expf(10.f * crossn) + nI));
        // intra_query
        float posq = g_qs[b * TT + tid];
        float nsq = 0.f;
        for (int t2 = 0; t2 < TT; t2++)
            if ((t2 >> 1) != b) nsq += __expf(10.f * g_qs[b * TT + t2]);
        vals[3] = -(10.f * posq - logf(__expf(10.f * posq) + nsq));
    }
    const float divi[4] = {128.f, 128.f, 256.f, 128.f};
    for (int m = 0; m < 4; m++) {
        red[tid] = vals[m];
        __syncthreads();
        for (int s = 128; s > 0; s >>= 1) {
            if (tid < s) red[tid] += red[tid + s];
            __syncthreads();
        }
        if (tid == 0) out[m] = red[0] / divi[m];
        __syncthreads();
    }
}

// ---------------- launch ----------------
extern "C" void kernel_launch(void* const* d_in, const int* in_sizes, int n_in,
                              void* d_out, int out_size) {
    const float* vid    = (const float*)d_in[0];  // (B, C, D, D)
    const float* qf     = (const float*)d_in[1];  // (B, C)
    const float* sf     = (const float*)d_in[2];  // (T, C)
    const float* iou2d  = (const float*)d_in[3];  // (B, D, D)
    const float* iou2ds = (const float*)d_in[4];  // (T, D, D)
    (void)in_sizes; (void)n_in; (void)out_size;

    k_topkstats<<<BB, 256>>>(iou2ds, vid);
    k_norm_q   <<<BB, 256>>>(qf);
    k_main     <<<dim3(NTILE, BB), 256>>>(vid, iou2d);
    k_norm_s   <<<TT, 256>>>(sf);
    k_qs       <<<BB, 256>>>();
    k_final    <<<1, 256>>>((float*)d_out);
}

// round 9
// speedup vs baseline: 1.1914x; 1.1419x over previous
#include <cuda_runtime.h>
#include <cuda_bf16.h>
#include <math.h>
#include <stdint.h>

// Problem constants (fixed by setup_inputs)
#define BB 64      // batch
#define CC 256     // channels
#define DD 64      // 2D map side
#define TT 128     // total sentences (B * n, n = 2)
#define PP 2080    // triu proposals
#define TPL 128    // proposals per tile (= GEMM M)
#define NTILE 17   // ceil(PP / TPL)
#define NBLK (BB * NTILE)
#define KCH 64     // K floats per chunk
#define NCHUNK (CC / KCH)  // 4
#define VROW 72    // smem row stride in bf16 (144B: frag loads conflict-free)

#define DYN_SMEM (128 * VROW * 2 * 2 + 64 * VROW * 2 * 2)  // 55296 B

// ---------------- scratch (device globals; fully overwritten every launch) ---
__device__ int   g_pk[TT];               // argmax p (triu order) per t
__device__ int   g_pkflat[TT];           // flat r*64+c position
__device__ float g_qn[BB * CC];          // normalized query feats
__device__ __nv_bfloat16 g_qbh[BB * CC]; // bf16 hi of qn
__device__ __nv_bfloat16 g_qbl[BB * CC]; // bf16 lo of qn
__device__ float g_sn[TT * CC];          // normalized sentence feats
__device__ float g_norm2k[TT];           // |v[b', pos_k(t)]|^2
__device__ float g_cross[BB];            // vk0 . vk1 raw dot
__device__ float g_sTop[TT * BB];        // cosine(topk_vf[t], qf_n[b])
__device__ float g_qs[BB * TT];          // qf_n[b] . sf_n[t']
__device__ float g_totQpart[NBLK * BB];
__device__ float g_posQpart[NBLK];
__device__ float g_negIpart[NBLK * 2];

// ---------------- mma.sync wrapper (bf16 x bf16 -> f32, m16n8k16) ----------
__device__ __forceinline__ void mma16816(float* d,
                                         uint32_t a0, uint32_t a1,
                                         uint32_t a2, uint32_t a3,
                                         uint32_t b0, uint32_t b1) {
    asm volatile(
        "mma.sync.aligned.m16n8k16.row.col.f32.bf16.bf16.f32 "
        "{%0,%1,%2,%3}, {%4,%5,%6,%7}, {%8,%9}, {%0,%1,%2,%3};"
        : "+f"(d[0]), "+f"(d[1]), "+f"(d[2]), "+f"(d[3])
        : "r"(a0), "r"(a1), "r"(a2), "r"(a3), "r"(b0), "r"(b1));
}

__device__ __forceinline__ uint32_t bf16pair(float lo, float hi) {
    __nv_bfloat162 h2(__float2bfloat16(lo), __float2bfloat16(hi));
    return *(uint32_t*)&h2;
}

// ---------------- topk (K=1) + topk-vector stats, fused per b' ----------------
__global__ void k_topkstats(const float* __restrict__ iou2ds,
                            const float* __restrict__ vid) {
    int b = blockIdx.x, tid = threadIdx.x;  // 256 threads
    __shared__ float bv[256]; __shared__ int bx[256];
    __shared__ int pkf[2];

    for (int j = 0; j < 2; j++) {
        int t = 2 * b + j;
        const float4* row = (const float4*)(iou2ds + (size_t)t * (DD * DD));
        float best = -1e30f; int bf = 0x3fffffff;
        for (int v = tid; v < 1024; v += 256) {
            float4 x = row[v];
            int f0 = v * 4;
            float vals[4] = {x.x, x.y, x.z, x.w};
            #pragma unroll
            for (int e = 0; e < 4; e++) {
                int f = f0 + e, r = f >> 6, c = f & 63;
                if (c >= r && vals[e] > best) { best = vals[e]; bf = f; }
            }
        }
        bv[tid] = best; bx[tid] = bf;
        __syncthreads();
        for (int s = 128; s > 0; s >>= 1) {
            if (tid < s) {
                if (bv[tid + s] > bv[tid] ||
                    (bv[tid + s] == bv[tid] && bx[tid + s] < bx[tid])) {
                    bv[tid] = bv[tid + s]; bx[tid] = bx[tid + s];
                }
            }
            __syncthreads();
        }
        if (tid == 0) {
            int f = bx[0], r = f >> 6, c = f & 63;
            g_pk[t] = r * 64 - (r * (r - 1)) / 2 + (c - r);
            g_pkflat[t] = f;
            pkf[j] = f;
        }
        __syncthreads();
    }

    int pk0 = pkf[0], pk1 = pkf[1];
    const float* vb = vid + (size_t)b * CC * (DD * DD);
    float v0 = vb[(size_t)tid * (DD * DD) + pk0];
    float v1 = vb[(size_t)tid * (DD * DD) + pk1];
    float a = v0 * v0, d2 = v1 * v1, x = v0 * v1;
    for (int o = 16; o > 0; o >>= 1) {
        a  += __shfl_xor_sync(0xffffffffu, a, o);
        d2 += __shfl_xor_sync(0xffffffffu, d2, o);
        x  += __shfl_xor_sync(0xffffffffu, x, o);
    }
    __shared__ float sa[8], sd[8], sx[8];
    if ((tid & 31) == 0) { sa[tid >> 5] = a; sd[tid >> 5] = d2; sx[tid >> 5] = x; }
    __syncthreads();
    if (tid == 0) {
        float ta = 0, td = 0, tc = 0;
        for (int w = 0; w < 8; w++) { ta += sa[w]; td += sd[w]; tc += sx[w]; }
        g_norm2k[2 * b] = ta; g_norm2k[2 * b + 1] = td; g_cross[b] = tc;
    }
}

// ---------------- row normalization (fused q + s) ----------------
__device__ __forceinline__ float blk_sumsq(float v) {
    float s = v * v;
    for (int o = 16; o > 0; o >>= 1) s += __shfl_xor_sync(0xffffffffu, s, o);
    __shared__ float ws[8];
    int tid = threadIdx.x;
    if ((tid & 31) == 0) ws[tid >> 5] = s;
    __syncthreads();
    return ws[0] + ws[1] + ws[2] + ws[3] + ws[4] + ws[5] + ws[6] + ws[7];
}

__global__ void k_norms(const float* __restrict__ q, const float* __restrict__ s) {
    int row = blockIdx.x, tid = threadIdx.x;
    if (row < BB) {
        float v = q[row * CC + tid];
        float inv = 1.0f / fmaxf(sqrtf(blk_sumsq(v)), 1e-12f);
        float nv = v * inv;
        g_qn[row * CC + tid] = nv;
        __nv_bfloat16 h = __float2bfloat16(nv);
        g_qbh[row * CC + tid] = h;
        g_qbl[row * CC + tid] = __float2bfloat16(nv - __bfloat162float(h));
    } else {
        int r = row - BB;
        float v = s[r * CC + tid];
        float inv = 1.0f / fmaxf(sqrtf(blk_sumsq(v)), 1e-12f);
        g_sn[r * CC + tid] = v * inv;
    }
}

// ---------------- qf_n @ sf_n^T (tiny) ----------------
__global__ void k_qs() {
    int b = blockIdx.x, tid = threadIdx.x;
    __shared__ float qsh[CC];
    qsh[tid] = g_qn[b * CC + tid];
    __syncthreads();
    int w = tid >> 5, lane = tid & 31;
    for (int t2 = w; t2 < TT; t2 += 8) {
        float a = 0.f;
        for (int c = lane; c < CC; c += 32) a += qsh[c] * g_sn[t2 * CC + c];
        for (int o = 16; o > 0; o >>= 1) a += __shfl_xor_sync(0xffffffffu, a, o);
        if (lane == 0) g_qs[b * TT + t2] = a;
    }
}

// ---------------- main fused pass: mma.sync bf16 hi/lo GEMM ----------------
// grid (NTILE, BB), 256 threads (8 warps). Warp w owns rows w*16..w*16+15.
// D[128p x 64q] = V . Qn^T via 3-term bf16 compensation. Stats ride the gather.
__global__ void __launch_bounds__(256) k_main(const float* __restrict__ vid,
                                              const float* __restrict__ iou2d) {
    extern __shared__ __align__(16) char dyn[];
    __nv_bfloat16* Vh = (__nv_bfloat16*)dyn;          // [128][VROW]
    __nv_bfloat16* Vl = Vh + 128 * VROW;
    __nv_bfloat16* Qh = Vl + 128 * VROW;              // [64][VROW]
    __nv_bfloat16* Ql = Qh + 64 * VROW;

    __shared__ float vk0s[CC], vk1s[CC];
    __shared__ int   posArr[TPL];
    __shared__ float ioul[TPL], invnS[TPL];
    __shared__ float statA[256], stat0[256], stat1[256];
    __shared__ float partQ[8][64];
    __shared__ float red[256];
    __shared__ float nb0s[TPL], nb1s[TPL];

    int tileIdx = blockIdx.x, bp = blockIdx.y;
    int p0 = tileIdx * TPL;
    int tid = threadIdx.x, wid = tid >> 5, lane = tid & 31;

    const float* vb = vid + (size_t)bp * CC * (DD * DD);
    int t0 = 2 * bp, t1 = t0 + 1;
    int pkI0 = g_pk[t0], pkI1 = g_pk[t1];
    int pf0 = g_pkflat[t0], pf1 = g_pkflat[t1];
    vk0s[tid] = vb[(size_t)tid * (DD * DD) + pf0];
    vk1s[tid] = vb[(size_t)tid * (DD * DD) + pf1];

    if (tid < TPL) {
        int pg = p0 + tid;
        int pc = pg < PP ? pg : PP - 1;  // clamp; masked in epilogue
        int r = (int)(64.5f - sqrtf(64.5f * 64.5f - 2.0f * (float)pc));
        while (r > 0  && r * 64 - (r * (r - 1)) / 2 > pc) r--;
        while (r < 63 && (r + 1) * 64 - ((r + 1) * r) / 2 <= pc) r++;
        int start = r * 64 - (r * (r - 1)) / 2;
        int pos = r * 64 + (r + (pc - start));
        posArr[tid] = pos;
        ioul[tid] = iou2d[bp * (DD * DD) + pos];
    }
    __syncthreads();

    int p = tid & 127, kh = tid >> 7;       // gather role: (proposal, k-half)
    const float* gp = vb + posArr[p];
    float an = 0.f, a0 = 0.f, a1 = 0.f;

    float acc[8][4] = {};                   // 8 n-blocks x 4 f32
    int g = lane >> 2, tg = lane & 3;       // fragment group ids

    for (int c = 0; c < NCHUNK; c++) {
        int kb = c * KCH;
        // ---- gather V, convert hi/lo, store, stats ----
        #pragma unroll
        for (int j = 0; j < 32; j += 4) {
            int k = kb + kh * 32 + j;
            float v0 = gp[(size_t)(k + 0) * (DD * DD)];
            float v1 = gp[(size_t)(k + 1) * (DD * DD)];
            float v2 = gp[(size_t)(k + 2) * (DD * DD)];
            float v3 = gp[(size_t)(k + 3) * (DD * DD)];
            an += v0 * v0 + v1 * v1 + v2 * v2 + v3 * v3;
            a0 += v0 * vk0s[k] + v1 * vk0s[k + 1] + v2 * vk0s[k + 2] + v3 * vk0s[k + 3];
            a1 += v0 * vk1s[k] + v1 * vk1s[k + 1] + v2 * vk1s[k + 2] + v3 * vk1s[k + 3];
            __nv_bfloat16 h0 = __float2bfloat16(v0), h1 = __float2bfloat16(v1);
            __nv_bfloat16 h2 = __float2bfloat16(v2), h3 = __float2bfloat16(v3);
            uint2 hb, lb;
            { __nv_bfloat162 t01(h0, h1), t23(h2, h3);
              hb.x = *(uint32_t*)&t01; hb.y = *(uint32_t*)&t23; }
            lb.x = bf16pair(v0 - __bfloat162float(h0), v1 - __bfloat162float(h1));
            lb.y = bf16pair(v2 - __bfloat162float(h2), v3 - __bfloat162float(h3));
            int so = p * VROW + kh * 32 + j;
            *(uint2*)&Vh[so] = hb;
            *(uint2*)&Vl[so] = lb;
        }
        // ---- Q tiles: 64 q x 64 k (pairs), coalesced ----
        #pragma unroll
        for (int i = 0; i < 8; i++) {
            int idx = tid + i * 256;          // 0..2047
            int q = idx >> 5, kp = idx & 31;
            *(uint32_t*)&Qh[q * VROW + kp * 2] = *(const uint32_t*)&g_qbh[q * CC + kb + kp * 2];
            *(uint32_t*)&Ql[q * VROW + kp * 2] = *(const uint32_t*)&g_qbl[q * CC + kb + kp * 2];
        }
        __syncthreads();

        // ---- MMA: warp w rows w*16.., all 64 cols, 4 k-steps ----
        int rA = wid * 16 + g;
        #pragma unroll
        for (int ks = 0; ks < 4; ks++) {
            int k0 = ks * 16;
            const __nv_bfloat16* ah = &Vh[rA * VROW + k0 + tg * 2];
            const __nv_bfloat16* al = &Vl[rA * VROW + k0 + tg * 2];
            uint32_t ah0 = *(const uint32_t*)(ah);
            uint32_t ah1 = *(const uint32_t*)(ah + 8 * VROW);
            uint32_t ah2 = *(const uint32_t*)(ah + 8);
            uint32_t ah3 = *(const uint32_t*)(ah + 8 * VROW + 8);
            uint32_t al0 = *(const uint32_t*)(al);
            uint32_t al1 = *(const uint32_t*)(al + 8 * VROW);
            uint32_t al2 = *(const uint32_t*)(al + 8);
            uint32_t al3 = *(const uint32_t*)(al + 8 * VROW + 8);
            #pragma unroll
            for (int nb = 0; nb < 8; nb++) {
                const __nv_bfloat16* bh = &Qh[(nb * 8 + g) * VROW + k0 + tg * 2];
                const __nv_bfloat16* bl = &Ql[(nb * 8 + g) * VROW + k0 + tg * 2];
                uint32_t bh0 = *(const uint32_t*)(bh);
                uint32_t bh1 = *(const uint32_t*)(bh + 8);
                uint32_t bl0 = *(const uint32_t*)(bl);
                uint32_t bl1 = *(const uint32_t*)(bl + 8);
                mma16816(acc[nb], ah0, ah1, ah2, ah3, bh0, bh1);
                mma16816(acc[nb], ah0, ah1, ah2, ah3, bl0, bl1);
                mma16816(acc[nb], al0, al1, al2, al3, bh0, bh1);
            }
        }
        __syncthreads();
    }

    // ---- stats combine (p owned by 2 threads: kh halves) ----
    statA[tid] = an; stat0[tid] = a0; stat1[tid] = a1;
    __syncthreads();
    if (tid < TPL) {
        float n2 = statA[tid] + statA[tid + 128];
        float inv = 1.0f / fmaxf(sqrtf(n2), 1e-12f);
        invnS[tid] = inv;
        float i0 = stat0[tid] + stat0[tid + 128];
        float i1 = stat1[tid] + stat1[tid + 128];
        bool negm = (p0 + tid < PP) && (ioul[tid] < 0.5f);
        float invk0 = 1.0f / fmaxf(sqrtf(g_norm2k[t0]), 1e-12f);
        float invk1 = 1.0f / fmaxf(sqrtf(g_norm2k[t1]), 1e-12f);
        nb0s[tid] = negm ? __expf(10.0f * i0 * inv * invk0) : 0.f;
        nb1s[tid] = negm ? __expf(10.0f * i1 * inv * invk1) : 0.f;
    }
    __syncthreads();

    // ---- epilogue: scores -> exp -> column partials ----
    int rl0 = wid * 16 + g, rl1 = rl0 + 8;
    int pg0 = p0 + rl0, pg1 = p0 + rl1;
    bool v0 = pg0 < PP, v1 = pg1 < PP;
    float in0 = invnS[rl0], in1 = invnS[rl1];
    bool pm0 = v0 && (ioul[rl0] > 0.5f), pm1 = v1 && (ioul[rl1] > 0.5f);
    bool w00 = (pg0 == pkI0), w01 = (pg0 == pkI1);
    bool w10 = (pg1 == pkI0), w11 = (pg1 == pkI1);

    float colSum[16];
    float posAcc = 0.f;
    #pragma unroll
    for (int nb = 0; nb < 8; nb++) {
        int n0 = nb * 8 + tg * 2, n1 = n0 + 1;
        float s00 = acc[nb][0] * in0, s01 = acc[nb][1] * in0;
        float s10 = acc[nb][2] * in1, s11 = acc[nb][3] * in1;
        float e00 = v0 ? __expf(10.f * s00) : 0.f;
        float e01 = v0 ? __expf(10.f * s01) : 0.f;
        float e10 = v1 ? __expf(10.f * s10) : 0.f;
        float e11 = v1 ? __expf(10.f * s11) : 0.f;
        colSum[2 * nb]     = e00 + e10;
        colSum[2 * nb + 1] = e01 + e11;
        if (n0 == bp) { if (pm0) posAcc += e00; if (pm1) posAcc += e10; }
        if (n1 == bp) { if (pm0) posAcc += e01; if (pm1) posAcc += e11; }
        if (w00) { g_sTop[t0 * BB + n0] = s00; g_sTop[t0 * BB + n1] = s01; }
        if (w01) { g_sTop[t1 * BB + n0] = s00; g_sTop[t1 * BB + n1] = s01; }
        if (w10) { g_sTop[t0 * BB + n0] = s10; g_sTop[t0 * BB + n1] = s11; }
        if (w11) { g_sTop[t1 * BB + n0] = s10; g_sTop[t1 * BB + n1] = s11; }
    }
    // reduce cols across the 8 lanes with same tg (lanes l, l^4, l^8, l^16)
    #pragma unroll
    for (int o = 4; o <= 16; o <<= 1) {
        #pragma unroll
        for (int i = 0; i < 16; i++)
            colSum[i] += __shfl_xor_sync(0xffffffffu, colSum[i], o);
    }
    if (lane < 4) {
        #pragma unroll
        for (int nb = 0; nb < 8; nb++) {
            partQ[wid][nb * 8 + lane * 2]     = colSum[2 * nb];
            partQ[wid][nb * 8 + lane * 2 + 1] = colSum[2 * nb + 1];
        }
    }
    red[tid] = posAcc;
    __syncthreads();

    int blk = bp * NTILE + tileIdx;
    if (tid < BB) {
        float s = 0.f;
        #pragma unroll
        for (int w = 0; w < 8; w++) s += partQ[w][tid];
        g_totQpart[blk * BB + tid] = s;
    }
    for (int s = 128; s > 0; s >>= 1) {
        if (tid < s) red[tid] += red[tid + s];
        __syncthreads();
    }
    if (tid == 0) g_posQpart[blk] = red[0];
    if (tid < 2) {
        const float* src = tid ? nb1s : nb0s;
        float s = 0.f;
        for (int pp = 0; pp < TPL; pp++) s += src[pp];
        g_negIpart[blk * 2 + tid] = s;
    }
}

// ---------------- final: assemble the 4 losses ----------------
__global__ void k_final(float* __restrict__ out) {
    __shared__ float totQ4[BB][4];
    __shared__ float totQ[BB], posQ[BB], negI[TT];
    __shared__ float red[256];
    int tid = threadIdx.x;  // 256

    {
        int q = tid >> 2, part = tid & 3;
        float s = 0.f;
        for (int blk = part; blk < NBLK; blk += 4) s += g_totQpart[blk * BB + q];
        totQ4[q][part] = s;
    }
    if (tid < BB) {
        float sp = 0.f;
        for (int ti = 0; ti < NTILE; ti++) sp += g_posQpart[tid * NTILE + ti];
        posQ[tid] = sp;
    }
    if (tid < TT) {
        int b = tid >> 1, j = tid & 1;
        float s = 0.f;
        for (int ti = 0; ti < NTILE; ti++) s += g_negIpart[(b * NTILE + ti) * 2 + j];
        negI[tid] = s;
    }
    __syncthreads();
    if (tid < BB) totQ[tid] = totQ4[tid][0] + totQ4[tid][1] + totQ4[tid][2] + totQ4[tid][3];
    __syncthreads();

    float vals[4] = {0.f, 0.f, 0.f, 0.f};
    if (tid < TT) {
        int b = tid >> 1;
        float pos = g_sTop[tid * BB + b];
        float pe = __expf(10.f * pos);
        float ns = 0.f;
        for (int q = 0; q < BB; q++)
            if (q != b) ns += __expf(10.f * g_sTop[tid * BB + q]);
        vals[0] = -(10.f * pos - logf(pe + ns));
        vals[1] = -(10.f * pos - logf(pe + (totQ[b] - posQ[b])));
        float inv0 = 1.f / fmaxf(sqrtf(g_norm2k[2 * b]), 1e-12f);
        float inv1 = 1.f / fmaxf(sqrtf(g_norm2k[2 * b + 1]), 1e-12f);
        float crossn = g_cross[b] * inv0 * inv1;
        float invt = (tid & 1) ? inv1 : inv0;
        float selfn = g_norm2k[tid] * invt * invt;
        float nI = negI[tid];
        vals[2] = -(10.f * selfn  - logf(__expf(10.f * selfn)  + nI))
                + -(10.f * crossn - logf(__expf(10.f * crossn) + nI));
        float posq = g_qs[b * TT + tid];
        float nsq = 0.f;
        for (int t2 = 0; t2 < TT; t2++)
            if ((t2 >> 1) != b) nsq += __expf(10.f * g_qs[b * TT + t2]);
        vals[3] = -(10.f * posq - logf(__expf(10.f * posq) + nsq));
    }
    const float divi[4] = {128.f, 128.f, 256.f, 128.f};
    for (int m = 0; m < 4; m++) {
        red[tid] = vals[m];
        __syncthreads();
        for (int s = 128; s > 0; s >>= 1) {
            if (tid < s) red[tid] += red[tid + s];
            __syncthreads();
        }
        if (tid == 0) out[m] = red[0] / divi[m];
        __syncthreads();
    }
}

// ---------------- launch (k_main 4th for the profile window) ----------------
extern "C" void kernel_launch(void* const* d_in, const int* in_sizes, int n_in,
                              void* d_out, int out_size) {
    const float* vid    = (const float*)d_in[0];
    const float* qf     = (const float*)d_in[1];
    const float* sf     = (const float*)d_in[2];
    const float* iou2d  = (const float*)d_in[3];
    const float* iou2ds = (const float*)d_in[4];
    (void)in_sizes; (void)n_in; (void)out_size;

    cudaFuncSetAttribute(k_main, cudaFuncAttributeMaxDynamicSharedMemorySize, DYN_SMEM);

    k_topkstats<<<BB, 256>>>(iou2ds, vid);
    k_norms    <<<BB + TT, 256>>>(qf, sf);
    k_qs       <<<BB, 256>>>();
    k_main     <<<dim3(NTILE, BB), 256, DYN_SMEM>>>(vid, iou2d);
    k_final    <<<1, 256>>>((float*)d_out);
}

// round 10
// speedup vs baseline: 1.3533x; 1.1359x over previous
#include <cuda_runtime.h>
#include <cuda_bf16.h>
#include <math.h>
#include <stdint.h>

// Problem constants (fixed by setup_inputs)
#define BB 64      // batch
#define CC 256     // channels
#define DD 64      // 2D map side
#define TT 128     // total sentences (B * n, n = 2)
#define PP 2080    // triu proposals
#define TPL 128    // proposals per tile (= GEMM M)
#define NTILE 17   // ceil(PP / TPL)
#define NBLK (BB * NTILE)
#define KCH 32     // K floats per chunk
#define NCHUNK (CC / KCH)  // 8
#define VR 40      // smem row stride in bf16 (80B rows; frag loads conflict-free)

// per buffer (bf16 elems): Vh 128*40=5120, Vl 5120, Qh 64*40=2560, Ql 2560
#define BUF_ELEMS 15360
#define DYN_SMEM (2 * BUF_ELEMS * 2)   // 61440 B

// ---------------- scratch (device globals; fully overwritten every launch) ---
__device__ int   g_pk[TT];               // argmax p (triu order) per t
__device__ int   g_pkflat[TT];           // flat r*64+c position
__device__ float g_qn[BB * CC];          // normalized query feats
__device__ __nv_bfloat16 g_qbh[BB * CC]; // bf16 hi of qn
__device__ __nv_bfloat16 g_qbl[BB * CC]; // bf16 lo of qn
__device__ float g_sn[TT * CC];          // normalized sentence feats
__device__ float g_norm2k[TT];           // |v[b', pos_k(t)]|^2
__device__ float g_cross[BB];            // vk0 . vk1 raw dot
__device__ float g_sTop[TT * BB];        // cosine(topk_vf[t], qf_n[b])
__device__ float g_qs[BB * TT];          // qf_n[b] . sf_n[t']
__device__ float g_totQpart[NBLK * BB];
__device__ float g_posQpart[NBLK];
__device__ float g_negIpart[NBLK * 2];

// ---------------- mma.sync wrapper (bf16 x bf16 -> f32, m16n8k16) ----------
__device__ __forceinline__ void mma16816(float* d,
                                         uint32_t a0, uint32_t a1,
                                         uint32_t a2, uint32_t a3,
                                         uint32_t b0, uint32_t b1) {
    asm volatile(
        "mma.sync.aligned.m16n8k16.row.col.f32.bf16.bf16.f32 "
        "{%0,%1,%2,%3}, {%4,%5,%6,%7}, {%8,%9}, {%0,%1,%2,%3};"
        : "+f"(d[0]), "+f"(d[1]), "+f"(d[2]), "+f"(d[3])
        : "r"(a0), "r"(a1), "r"(a2), "r"(a3), "r"(b0), "r"(b1));
}

__device__ __forceinline__ uint32_t bf16pair(float lo, float hi) {
    __nv_bfloat162 h2(__float2bfloat16(lo), __float2bfloat16(hi));
    return *(uint32_t*)&h2;
}

// ---------------- topk (K=1) + topk-vector stats, fused per b' ----------------
__global__ void k_topkstats(const float* __restrict__ iou2ds,
                            const float* __restrict__ vid) {
    int b = blockIdx.x, tid = threadIdx.x;  // 256 threads
    __shared__ float bv[256]; __shared__ int bx[256];
    __shared__ int pkf[2];

    for (int j = 0; j < 2; j++) {
        int t = 2 * b + j;
        const float4* row = (const float4*)(iou2ds + (size_t)t * (DD * DD));
        float best = -1e30f; int bf = 0x3fffffff;
        for (int v = tid; v < 1024; v += 256) {
            float4 x = row[v];
            int f0 = v * 4;
            float vals[4] = {x.x, x.y, x.z, x.w};
            #pragma unroll
            for (int e = 0; e < 4; e++) {
                int f = f0 + e, r = f >> 6, c = f & 63;
                if (c >= r && vals[e] > best) { best = vals[e]; bf = f; }
            }
        }
        bv[tid] = best; bx[tid] = bf;
        __syncthreads();
        for (int s = 128; s > 0; s >>= 1) {
            if (tid < s) {
                if (bv[tid + s] > bv[tid] ||
                    (bv[tid + s] == bv[tid] && bx[tid + s] < bx[tid])) {
                    bv[tid] = bv[tid + s]; bx[tid] = bx[tid + s];
                }
            }
            __syncthreads();
        }
        if (tid == 0) {
            int f = bx[0], r = f >> 6, c = f & 63;
            g_pk[t] = r * 64 - (r * (r - 1)) / 2 + (c - r);
            g_pkflat[t] = f;
            pkf[j] = f;
        }
        __syncthreads();
    }

    int pk0 = pkf[0], pk1 = pkf[1];
    const float* vb = vid + (size_t)b * CC * (DD * DD);
    float v0 = vb[(size_t)tid * (DD * DD) + pk0];
    float v1 = vb[(size_t)tid * (DD * DD) + pk1];
    float a = v0 * v0, d2 = v1 * v1, x = v0 * v1;
    for (int o = 16; o > 0; o >>= 1) {
        a  += __shfl_xor_sync(0xffffffffu, a, o);
        d2 += __shfl_xor_sync(0xffffffffu, d2, o);
        x  += __shfl_xor_sync(0xffffffffu, x, o);
    }
    __shared__ float sa[8], sd[8], sx[8];
    if ((tid & 31) == 0) { sa[tid >> 5] = a; sd[tid >> 5] = d2; sx[tid >> 5] = x; }
    __syncthreads();
    if (tid == 0) {
        float ta = 0, td = 0, tc = 0;
        for (int w = 0; w < 8; w++) { ta += sa[w]; td += sd[w]; tc += sx[w]; }
        g_norm2k[2 * b] = ta; g_norm2k[2 * b + 1] = td; g_cross[b] = tc;
    }
}

// ---------------- row normalization (fused q + s) ----------------
__device__ __forceinline__ float blk_sumsq(float v) {
    float s = v * v;
    for (int o = 16; o > 0; o >>= 1) s += __shfl_xor_sync(0xffffffffu, s, o);
    __shared__ float ws[8];
    int tid = threadIdx.x;
    if ((tid & 31) == 0) ws[tid >> 5] = s;
    __syncthreads();
    return ws[0] + ws[1] + ws[2] + ws[3] + ws[4] + ws[5] + ws[6] + ws[7];
}

__global__ void k_norms(const float* __restrict__ q, const float* __restrict__ s) {
    int row = blockIdx.x, tid = threadIdx.x;
    if (row < BB) {
        float v = q[row * CC + tid];
        float inv = 1.0f / fmaxf(sqrtf(blk_sumsq(v)), 1e-12f);
        float nv = v * inv;
        g_qn[row * CC + tid] = nv;
        __nv_bfloat16 h = __float2bfloat16(nv);
        g_qbh[row * CC + tid] = h;
        g_qbl[row * CC + tid] = __float2bfloat16(nv - __bfloat162float(h));
    } else {
        int r = row - BB;
        float v = s[r * CC + tid];
        float inv = 1.0f / fmaxf(sqrtf(blk_sumsq(v)), 1e-12f);
        g_sn[r * CC + tid] = v * inv;
    }
}

// ---------------- qf_n @ sf_n^T (tiny) ----------------
__global__ void k_qs() {
    int b = blockIdx.x, tid = threadIdx.x;
    __shared__ float qsh[CC];
    qsh[tid] = g_qn[b * CC + tid];
    __syncthreads();
    int w = tid >> 5, lane = tid & 31;
    for (int t2 = w; t2 < TT; t2 += 8) {
        float a = 0.f;
        for (int c = lane; c < CC; c += 32) a += qsh[c] * g_sn[t2 * CC + c];
        for (int o = 16; o > 0; o >>= 1) a += __shfl_xor_sync(0xffffffffu, a, o);
        if (lane == 0) g_qs[b * TT + t2] = a;
    }
}

// ---------------- main fused pass: pipelined mma.sync bf16 hi/lo GEMM -------
// grid (NTILE, BB), 256 threads (8 warps). Double-buffered smem tiles,
// register-prefetched gather overlapping the MMA. One barrier per chunk.
__global__ void __launch_bounds__(256) k_main(const float* __restrict__ vid,
                                              const float* __restrict__ iou2d) {
    extern __shared__ __align__(16) char dyn[];
    __nv_bfloat16* sbase = (__nv_bfloat16*)dyn;

    __shared__ float vk0s[CC], vk1s[CC];
    __shared__ int   posArr[TPL];
    __shared__ float ioul[TPL], invnS[TPL];
    __shared__ float statA[256], stat0[256], stat1[256];
    __shared__ float partQ[8][64];
    __shared__ float red[256];
    __shared__ float nb0s[TPL], nb1s[TPL];

    int tileIdx = blockIdx.x, bp = blockIdx.y;
    int p0 = tileIdx * TPL;
    int tid = threadIdx.x, wid = tid >> 5, lane = tid & 31;

    const float* vb = vid + (size_t)bp * CC * (DD * DD);
    int t0 = 2 * bp, t1 = t0 + 1;
    int pkI0 = g_pk[t0], pkI1 = g_pk[t1];
    int pf0 = g_pkflat[t0], pf1 = g_pkflat[t1];
    vk0s[tid] = vb[(size_t)tid * (DD * DD) + pf0];
    vk1s[tid] = vb[(size_t)tid * (DD * DD) + pf1];

    if (tid < TPL) {
        int pg = p0 + tid;
        int pc = pg < PP ? pg : PP - 1;  // clamp; masked in epilogue
        int r = (int)(64.5f - sqrtf(64.5f * 64.5f - 2.0f * (float)pc));
        while (r > 0  && r * 64 - (r * (r - 1)) / 2 > pc) r--;
        while (r < 63 && (r + 1) * 64 - ((r + 1) * r) / 2 <= pc) r++;
        int start = r * 64 - (r * (r - 1)) / 2;
        int pos = r * 64 + (r + (pc - start));
        posArr[tid] = pos;
        ioul[tid] = iou2d[bp * (DD * DD) + pos];
    }
    __syncthreads();

    int p = tid & 127, kh = tid >> 7;       // gather role: (proposal, k-half of 16)
    const float* gp = vb + posArr[p];
    float an = 0.f, a0 = 0.f, a1 = 0.f;

    float acc[8][4] = {};                   // 8 n-blocks x 4 f32
    int g = lane >> 2, tg = lane & 3;       // fragment group ids

    // prefetch chunk 0
    float pf[16];
    #pragma unroll
    for (int j = 0; j < 16; j++)
        pf[j] = gp[(size_t)(kh * 16 + j) * (DD * DD)];

    for (int c = 0; c < NCHUNK; c++) {
        int kb = c * KCH;
        int buf = c & 1;
        __nv_bfloat16* Vh = sbase + buf * BUF_ELEMS;
        __nv_bfloat16* Vl = Vh + 5120;
        __nv_bfloat16* Qh = Vh + 10240;
        __nv_bfloat16* Ql = Vh + 12800;

        // ---- convert prefetched V -> smem (hi/lo), stats ride along ----
        #pragma unroll
        for (int j = 0; j < 16; j += 4) {
            int k = kb + kh * 16 + j;
            float v0 = pf[j], v1 = pf[j + 1], v2 = pf[j + 2], v3 = pf[j + 3];
            an += v0 * v0 + v1 * v1 + v2 * v2 + v3 * v3;
            a0 += v0 * vk0s[k] + v1 * vk0s[k + 1] + v2 * vk0s[k + 2] + v3 * vk0s[k + 3];
            a1 += v0 * vk1s[k] + v1 * vk1s[k + 1] + v2 * vk1s[k + 2] + v3 * vk1s[k + 3];
            __nv_bfloat16 h0 = __float2bfloat16(v0), h1 = __float2bfloat16(v1);
            __nv_bfloat16 h2 = __float2bfloat16(v2), h3 = __float2bfloat16(v3);
            uint2 hb, lb;
            { __nv_bfloat162 t01(h0, h1), t23(h2, h3);
              hb.x = *(uint32_t*)&t01; hb.y = *(uint32_t*)&t23; }
            lb.x = bf16pair(v0 - __bfloat162float(h0), v1 - __bfloat162float(h1));
            lb.y = bf16pair(v2 - __bfloat162float(h2), v3 - __bfloat162float(h3));
            int so = p * VR + kh * 16 + j;
            *(uint2*)&Vh[so] = hb;
            *(uint2*)&Vl[so] = lb;
        }
        // ---- Q tiles: 64 q x 16 u32-pairs each, coalesced (L1-hot) ----
        #pragma unroll
        for (int i = 0; i < 4; i++) {
            int idx = tid + i * 256;          // 0..1023
            int q = idx >> 4, kp = idx & 15;
            *(uint32_t*)&Qh[q * VR + kp * 2] = *(const uint32_t*)&g_qbh[q * CC + kb + kp * 2];
            *(uint32_t*)&Ql[q * VR + kp * 2] = *(const uint32_t*)&g_qbl[q * CC + kb + kp * 2];
        }
        __syncthreads();

        // ---- issue next chunk's gather (overlaps MMA below) ----
        if (c + 1 < NCHUNK) {
            int kn = (c + 1) * KCH + kh * 16;
            #pragma unroll
            for (int j = 0; j < 16; j++)
                pf[j] = gp[(size_t)(kn + j) * (DD * DD)];
        }

        // ---- MMA: warp w rows w*16.., all 64 cols, 2 k-steps ----
        int rA = wid * 16 + g;
        #pragma unroll
        for (int ks = 0; ks < 2; ks++) {
            int k0 = ks * 16;
            const __nv_bfloat16* ah = &Vh[rA * VR + k0 + tg * 2];
            const __nv_bfloat16* al = &Vl[rA * VR + k0 + tg * 2];
            uint32_t ah0 = *(const uint32_t*)(ah);
            uint32_t ah1 = *(const uint32_t*)(ah + 8 * VR);
            uint32_t ah2 = *(const uint32_t*)(ah + 8);
            uint32_t ah3 = *(const uint32_t*)(ah + 8 * VR + 8);
            uint32_t al0 = *(const uint32_t*)(al);
            uint32_t al1 = *(const uint32_t*)(al + 8 * VR);
            uint32_t al2 = *(const uint32_t*)(al + 8);
            uint32_t al3 = *(const uint32_t*)(al + 8 * VR + 8);
            #pragma unroll
            for (int nb = 0; nb < 8; nb++) {
                const __nv_bfloat16* bh = &Qh[(nb * 8 + g) * VR + k0 + tg * 2];
                const __nv_bfloat16* bl = &Ql[(nb * 8 + g) * VR + k0 + tg * 2];
                uint32_t bh0 = *(const uint32_t*)(bh);
                uint32_t bh1 = *(const uint32_t*)(bh + 8);
                uint32_t bl0 = *(const uint32_t*)(bl);
                uint32_t bl1 = *(const uint32_t*)(bl + 8);
                mma16816(acc[nb], ah0, ah1, ah2, ah3, bh0, bh1);
                mma16816(acc[nb], ah0, ah1, ah2, ah3, bl0, bl1);
                mma16816(acc[nb], al0, al1, al2, al3, bh0, bh1);
            }
        }
        // no trailing barrier: next iteration writes the other buffer, and
        // any warp reaching convert(c+2) has passed sync(c+1), which is after
        // every warp's MMA(c) in program order.
    }

    // ---- stats combine (p owned by 2 threads: kh halves) ----
    statA[tid] = an; stat0[tid] = a0; stat1[tid] = a1;
    __syncthreads();
    if (tid < TPL) {
        float n2 = statA[tid] + statA[tid + 128];
        float inv = 1.0f / fmaxf(sqrtf(n2), 1e-12f);
        invnS[tid] = inv;
        float i0 = stat0[tid] + stat0[tid + 128];
        float i1 = stat1[tid] + stat1[tid + 128];
        bool negm = (p0 + tid < PP) && (ioul[tid] < 0.5f);
        float invk0 = 1.0f / fmaxf(sqrtf(g_norm2k[t0]), 1e-12f);
        float invk1 = 1.0f / fmaxf(sqrtf(g_norm2k[t1]), 1e-12f);
        nb0s[tid] = negm ? __expf(10.0f * i0 * inv * invk0) : 0.f;
        nb1s[tid] = negm ? __expf(10.0f * i1 * inv * invk1) : 0.f;
    }
    __syncthreads();

    // ---- epilogue: scores -> exp -> column partials ----
    int rl0 = wid * 16 + g, rl1 = rl0 + 8;
    int pg0 = p0 + rl0, pg1 = p0 + rl1;
    bool v0 = pg0 < PP, v1 = pg1 < PP;
    float in0 = invnS[rl0], in1 = invnS[rl1];
    bool pm0 = v0 && (ioul[rl0] > 0.5f), pm1 = v1 && (ioul[rl1] > 0.5f);
    bool w00 = (pg0 == pkI0), w01 = (pg0 == pkI1);
    bool w10 = (pg1 == pkI0), w11 = (pg1 == pkI1);

    float colSum[16];
    float posAcc = 0.f;
    #pragma unroll
    for (int nb = 0; nb < 8; nb++) {
        int n0 = nb * 8 + tg * 2, n1 = n0 + 1;
        float s00 = acc[nb][0] * in0, s01 = acc[nb][1] * in0;
        float s10 = acc[nb][2] * in1, s11 = acc[nb][3] * in1;
        float e00 = v0 ? __expf(10.f * s00) : 0.f;
        float e01 = v0 ? __expf(10.f * s01) : 0.f;
        float e10 = v1 ? __expf(10.f * s10) : 0.f;
        float e11 = v1 ? __expf(10.f * s11) : 0.f;
        colSum[2 * nb]     = e00 + e10;
        colSum[2 * nb + 1] = e01 + e11;
        if (n0 == bp) { if (pm0) posAcc += e00; if (pm1) posAcc += e10; }
        if (n1 == bp) { if (pm0) posAcc += e01; if (pm1) posAcc += e11; }
        if (w00) { g_sTop[t0 * BB + n0] = s00; g_sTop[t0 * BB + n1] = s01; }
        if (w01) { g_sTop[t1 * BB + n0] = s00; g_sTop[t1 * BB + n1] = s01; }
        if (w10) { g_sTop[t0 * BB + n0] = s10; g_sTop[t0 * BB + n1] = s11; }
        if (w11) { g_sTop[t1 * BB + n0] = s10; g_sTop[t1 * BB + n1] = s11; }
    }
    // reduce cols across the 8 lanes with same tg
    #pragma unroll
    for (int o = 4; o <= 16; o <<= 1) {
        #pragma unroll
        for (int i = 0; i < 16; i++)
            colSum[i] += __shfl_xor_sync(0xffffffffu, colSum[i], o);
    }
    if (lane < 4) {
        #pragma unroll
        for (int nb = 0; nb < 8; nb++) {
            partQ[wid][nb * 8 + lane * 2]     = colSum[2 * nb];
            partQ[wid][nb * 8 + lane * 2 + 1] = colSum[2 * nb + 1];
        }
    }
    red[tid] = posAcc;
    __syncthreads();

    int blk = bp * NTILE + tileIdx;
    if (tid < BB) {
        float s = 0.f;
        #pragma unroll
        for (int w = 0; w < 8; w++) s += partQ[w][tid];
        g_totQpart[blk * BB + tid] = s;
    }
    for (int s = 128; s > 0; s >>= 1) {
        if (tid < s) red[tid] += red[tid + s];
        __syncthreads();
    }
    if (tid == 0) g_posQpart[blk] = red[0];
    if (tid < 2) {
        const float* src = tid ? nb1s : nb0s;
        float s = 0.f;
        for (int pp = 0; pp < TPL; pp++) s += src[pp];
        g_negIpart[blk * 2 + tid] = s;
    }
}

// ---------------- final: assemble the 4 losses ----------------
__global__ void k_final(float* __restrict__ out) {
    __shared__ float totQ4[BB][4];
    __shared__ float totQ[BB], posQ[BB], negI[TT];
    __shared__ float red[256];
    int tid = threadIdx.x;  // 256

    {
        int q = tid >> 2, part = tid & 3;
        float s = 0.f;
        for (int blk = part; blk < NBLK; blk += 4) s += g_totQpart[blk * BB + q];
        totQ4[q][part] = s;
    }
    if (tid < BB) {
        float sp = 0.f;
        for (int ti = 0; ti < NTILE; ti++) sp += g_posQpart[tid * NTILE + ti];
        posQ[tid] = sp;
    }
    if (tid < TT) {
        int b = tid >> 1, j = tid & 1;
        float s = 0.f;
        for (int ti = 0; ti < NTILE; ti++) s += g_negIpart[(b * NTILE + ti) * 2 + j];
        negI[tid] = s;
    }
    __syncthreads();
    if (tid < BB) totQ[tid] = totQ4[tid][0] + totQ4[tid][1] + totQ4[tid][2] + totQ4[tid][3];
    __syncthreads();

    float vals[4] = {0.f, 0.f, 0.f, 0.f};
    if (tid < TT) {
        int b = tid >> 1;
        float pos = g_sTop[tid * BB + b];
        float pe = __expf(10.f * pos);
        float ns = 0.f;
        for (int q = 0; q < BB; q++)
            if (q != b) ns += __expf(10.f * g_sTop[tid * BB + q]);
        vals[0] = -(10.f * pos - logf(pe + ns));
        vals[1] = -(10.f * pos - logf(pe + (totQ[b] - posQ[b])));
        float inv0 = 1.f / fmaxf(sqrtf(g_norm2k[2 * b]), 1e-12f);
        float inv1 = 1.f / fmaxf(sqrtf(g_norm2k[2 * b + 1]), 1e-12f);
        float crossn = g_cross[b] * inv0 * inv1;
        float invt = (tid & 1) ? inv1 : inv0;
        float selfn = g_norm2k[tid] * invt * invt;
        float nI = negI[tid];
        vals[2] = -(10.f * selfn  - logf(__expf(10.f * selfn)  + nI))
                + -(10.f * crossn - logf(__expf(10.f * crossn) + nI));
        float posq = g_qs[b * TT + tid];
        float nsq = 0.f;
        for (int t2 = 0; t2 < TT; t2++)
            if ((t2 >> 1) != b) nsq += __expf(10.f * g_qs[b * TT + t2]);
        vals[3] = -(10.f * posq - logf(__expf(10.f * posq) + nsq));
    }
    const float divi[4] = {128.f, 128.f, 256.f, 128.f};
    for (int m = 0; m < 4; m++) {
        red[tid] = vals[m];
        __syncthreads();
        for (int s = 128; s > 0; s >>= 1) {
            if (tid < s) red[tid] += red[tid + s];
            __syncthreads();
        }
        if (tid == 0) out[m] = red[0] / divi[m];
        __syncthreads();
    }
}

// ---------------- launch (k_main 4th for the profile window) ----------------
extern "C" void kernel_launch(void* const* d_in, const int* in_sizes, int n_in,
                              void* d_out, int out_size) {
    const float* vid    = (const float*)d_in[0];
    const float* qf     = (const float*)d_in[1];
    const float* sf     = (const float*)d_in[2];
    const float* iou2d  = (const float*)d_in[3];
    const float* iou2ds = (const float*)d_in[4];
    (void)in_sizes; (void)n_in; (void)out_size;

    cudaFuncSetAttribute(k_main, cudaFuncAttributeMaxDynamicSharedMemorySize, DYN_SMEM);

    k_topkstats<<<BB, 256>>>(iou2ds, vid);
    k_norms    <<<BB + TT, 256>>>(qf, sf);
    k_qs       <<<BB, 256>>>();
    k_main     <<<dim3(NTILE, BB), 256, DYN_SMEM>>>(vid, iou2d);
    k_final    <<<1, 256>>>((float*)d_out);
}